// round 9
// baseline (speedup 1.0000x reference)
#include <cuda_runtime.h>

#define HH    512
#define WW    512
#define HW    (HH * WW)
#define PAD   8
#define NKH   32
#define NKW   32
#define NK    1024
#define NC    33            // stride cells per dim (528/16)
#define BATCH 64
#define RPAD  36            // padded smem row (words): conflict-free LDS.128

// Init: out[b,n] = bias[n], vectorized. Full overwrite -> replay idempotent.
__global__ __launch_bounds__(256) void bslc_init(
    const float4* __restrict__ bias4, float4* __restrict__ out4)
{
    const int idx = blockIdx.x * 256 + threadIdx.x;   // 16384 float4 slots
    out4[idx] = bias4[idx & 255];
}

// One block per 16x16 stride cell, 512 threads (16 warps).
// Cell (Ri,Ci) covers padded pixels [16Ri,16Ri+16) x [16Ci,16Ci+16); these
// feed windows (Ri-i, Ci-j), i,j in {0,1}, at kernel offsets (dy+16i,
// dx+16j) -> quadrants q = i*2+j.
//
// Warp w: row-half h = w>>3, batches 8*(w&7)..+7. Lane owns ONE pixel-quad.
// The 4KB of quadrant weights is staged in smem once per block (reused by
// all batches; conflict-free LDS.128). All 8 batches' x float4 are
// front-batched into registers (MLP=8). Partials go through a conflict-free
// smem transpose in TWO 4-batch passes (sred fits 36KB); 128 threads per
// pass each do one atomicAdd into bias-initialized out (4 per (b,n) total).
__global__ __launch_bounds__(512, 2) void bslc_main(
    const float* __restrict__ x,       // (64,1,512,512)
    const float* __restrict__ weight,  // (NK,1024)
    float* __restrict__ out)           // (64,NK) = bias-initialized
{
    __shared__ __align__(16) float w_s[4][16][16];        // 4KB quadrant weights
    __shared__ __align__(16) float sred[16][4][4][RPAD];  // 36KB partials

    const int cell = blockIdx.x;
    const int Ri = cell / NC, Ci = cell % NC;
    const int tid  = threadIdx.x;
    const int lane = tid & 31;
    const int warp = tid >> 5;
    const int h    = warp >> 3;        // cell row-half
    const int wlow = warp & 7;         // batch-octet index

    // Quadrant windows + validity (uniform across block, full 4-sided check)
    int nq[4]; bool vq[4];
#pragma unroll
    for (int q = 0; q < 4; q++) {
        const int r = Ri - (q >> 1), c = Ci - (q & 1);
        vq[q] = (r >= 0) && (r < NKH) && (c >= 0) && (c < NKW);
        nq[q] = vq[q] ? (r * NKW + c) : 0;
    }

    // Lane's pixel-quad
    const int dy  = h * 8 + (lane >> 2);
    const int dx4 = (lane & 3) << 2;
    const int uy  = Ri * 16 + dy  - PAD;
    const int ux  = Ci * 16 + dx4 - PAD;
    const bool ok = ((unsigned)uy < (unsigned)HH) &&
                    ((unsigned)ux <= (unsigned)(WW - 4));
    const int off = uy * WW + ux;

    // Front-batched x loads: 8 independent LDG.128 per warp (MLP = 8)
    const float* __restrict__ xw = x + (size_t)(wlow * 8) * HW + off;
    float4 xv[8];
#pragma unroll
    for (int t = 0; t < 8; t++) {
        xv[t] = make_float4(0.f, 0.f, 0.f, 0.f);
        if (ok) xv[t] = *reinterpret_cast<const float4*>(xw + (size_t)t * HW);
    }

    // Cooperative weight stage: 1024 floats, 2 per thread
    {
        int e = tid;
#pragma unroll
        for (int k = 0; k < 2; k++, e += 512) {
            const int q  = e >> 8;
            const int rr = (e >> 4) & 15;
            const int cc = e & 15;
            float wv = 0.f;
            if (vq[q])
                wv = weight[nq[q] * 1024
                            + (rr + 16 * (q >> 1)) * 32
                            + (cc + 16 * (q & 1))];
            w_s[q][rr][cc] = wv;
        }
    }
    __syncthreads();

#pragma unroll
    for (int p = 0; p < 2; p++) {
        // Phase 1: partials for batches p*4..p*4+3 of each octet
#pragma unroll
        for (int q = 0; q < 4; q++) {
            const float4 wq = *reinterpret_cast<const float4*>(&w_s[q][dy][dx4]);
#pragma unroll
            for (int tp = 0; tp < 4; tp++) {
                const float4 xt = xv[p * 4 + tp];
                const float s =
                    fmaf(xt.x, wq.x,
                    fmaf(xt.y, wq.y,
                    fmaf(xt.z, wq.z, xt.w * wq.w)));
                sred[warp][tp][q][lane] = s;     // conflict-free STS.32
            }
        }
        __syncthreads();

        // Phase 2: 128 threads -> (octet wl, tp, quadrant q)
        if (tid < 128) {
            const int q  = tid & 3;
            const int lb = tid >> 2;          // 0..31
            const int wl = lb >> 2, tp = lb & 3;
            const float4* r0 = reinterpret_cast<const float4*>(&sred[wl    ][tp][q][0]);
            const float4* r1 = reinterpret_cast<const float4*>(&sred[8 + wl][tp][q][0]);
            float4 s4 = make_float4(0.f, 0.f, 0.f, 0.f);
#pragma unroll
            for (int i = 0; i < 8; i++) {
                const float4 a = r0[i], b4 = r1[i];
                s4.x += a.x + b4.x; s4.y += a.y + b4.y;
                s4.z += a.z + b4.z; s4.w += a.w + b4.w;
            }
            const float s = (s4.x + s4.y) + (s4.z + s4.w);

            const int b = wl * 8 + p * 4 + tp;
            const int r = Ri - (q >> 1), c = Ci - (q & 1);
            if (r >= 0 && r < NKH && c >= 0 && c < NKW)
                atomicAdd(out + (size_t)b * NK + r * NKW + c, s);
        }
        if (p == 0) __syncthreads();          // sred reused by pass 1
    }
}

extern "C" void kernel_launch(void* const* d_in, const int* in_sizes, int n_in,
                              void* d_out, int out_size)
{
    const float* x      = (const float*)d_in[0];   // (64,1,512,512) fp32
    const float* weight = (const float*)d_in[1];   // (1024,1024)    fp32
    const float* bias   = (const float*)d_in[2];   // (1024,)        fp32
    float*       out    = (float*)d_out;           // (64,32,32)     fp32

    bslc_init<<<(BATCH * NK) / (256 * 4), 256>>>(
        (const float4*)bias, (float4*)out);

    bslc_main<<<NC * NC, 512>>>(x, weight, out);
}

// round 10
// speedup vs baseline: 1.2145x; 1.2145x over previous
#include <cuda_runtime.h>

#define HH    512
#define WW    512
#define HW    (HH * WW)
#define PAD   8
#define NKH   32
#define NKW   32
#define NK    1024
#define NC    33            // stride cells per dim (528/16)
#define BATCH 64
#define RPAD  36            // lane-row stride (words): conflict-free LDS.128

// Init: out[b,n] = bias[n], vectorized. Full overwrite -> replay idempotent.
__global__ __launch_bounds__(256) void bslc_init(
    const float4* __restrict__ bias4, float4* __restrict__ out4)
{
    const int idx = blockIdx.x * 256 + threadIdx.x;   // 16384 float4 slots
    out4[idx] = bias4[idx & 255];
}

// Block = (16x16 stride cell, batch-half of 32). Cell (Ri,Ci) covers padded
// pixels [16Ri,16Ri+16)x[16Ci,16Ci+16); these feed windows (Ri-i, Ci-j),
// i,j in {0,1}, at kernel offsets (dy+16i, dx+16j) -> quadrants q=i*2+j.
//
// Warp = (row-half h = w&1, batch-octet bg = w>>1). Lane owns ONE pixel-quad
// -> 16 weight regs, leaving room to front-batch all 8 batches' float4
// (8 independent LDG.128 in flight, MLP=8). Per batch: 16 FMA + 4 stride-1
// STS. Phase 2: warps 0-3 (q = warp, b = lane) sum 16 conflict-free LDS.128
// (lane stride 36 words) and do one atomicAdd into bias-initialized out
// (4 atomics per (b,n) total, same as the best round).
__global__ __launch_bounds__(256, 4) void bslc_main(
    const float* __restrict__ x,       // (64,1,512,512)
    const float* __restrict__ weight,  // (NK,1024)
    float* __restrict__ out)           // (64,NK) = bias-initialized
{
    // [q][h][bg][t][lane + pad]  (rows 16B-aligned, lane-stride 36 words)
    __shared__ __align__(16) float sred[4][2][4][8][RPAD];

    const int cell = blockIdx.x;
    const int B0   = blockIdx.y * 32;      // batch-half base
    const int Ri = cell / NC, Ci = cell % NC;
    const int tid  = threadIdx.x;
    const int lane = tid & 31;
    const int warp = tid >> 5;
    const int h    = warp & 1;             // cell row-half
    const int bg   = warp >> 1;            // batch-octet (0..3)

    // Lane's pixel-quad within its half-cell
    const int dy  = h * 8 + (lane >> 2);
    const int dx4 = (lane & 3) << 2;
    const int uy  = Ri * 16 + dy  - PAD;
    const int ux  = Ci * 16 + dx4 - PAD;
    const bool ok = ((unsigned)uy < (unsigned)HH) &&
                    ((unsigned)ux <= (unsigned)(WW - 4));
    const int off = uy * WW + ux;

    // Front-batch all 8 batches' x: 8 independent LDG.128 (MLP = 8)
    const float* __restrict__ xw = x + (size_t)(B0 + bg * 8) * HW + off;
    float4 xv[8];
#pragma unroll
    for (int t = 0; t < 8; t++) {
        xv[t] = make_float4(0.f, 0.f, 0.f, 0.f);
        if (ok) xv[t] = *reinterpret_cast<const float4*>(xw + (size_t)t * HW);
    }

    // Quadrant windows + weights (4 float4/lane; full 4-sided check)
    float4 wq[4];
#pragma unroll
    for (int q = 0; q < 4; q++) {
        const int r = Ri - (q >> 1), c = Ci - (q & 1);
        const bool v = (r >= 0) && (r < NKH) && (c >= 0) && (c < NKW);
        float4 w = make_float4(0.f, 0.f, 0.f, 0.f);
        if (v)
            w = *reinterpret_cast<const float4*>(
                    weight + (r * NKW + c) * 1024
                           + (dy  + 16 * (q >> 1)) * 32
                           + (dx4 + 16 * (q & 1)));
        wq[q] = w;
    }

    // Phase 1: 16 FMAs + 4 STS per batch
#pragma unroll
    for (int t = 0; t < 8; t++) {
#pragma unroll
        for (int q = 0; q < 4; q++) {
            const float s =
                fmaf(xv[t].x, wq[q].x,
                fmaf(xv[t].y, wq[q].y,
                fmaf(xv[t].z, wq[q].z, xv[t].w * wq[q].w)));
            sred[q][h][bg][t][lane] = s;       // stride-1, conflict-free
        }
    }

    __syncthreads();

    // Phase 2: warps 0-3; q = warp, b = lane (0..31 within batch-half)
    if (tid < 128) {
        const int q = tid >> 5;
        const int b = tid & 31;               // = bg*8 + t
        const float* r0 = &sred[q][0][0][0][0] + b * RPAD;
        const float* r1 = &sred[q][1][0][0][0] + b * RPAD;
        float4 s4 = make_float4(0.f, 0.f, 0.f, 0.f);
#pragma unroll
        for (int i = 0; i < 8; i++) {
            const float4 a  = reinterpret_cast<const float4*>(r0)[i];
            const float4 b4 = reinterpret_cast<const float4*>(r1)[i];
            s4.x += a.x + b4.x; s4.y += a.y + b4.y;
            s4.z += a.z + b4.z; s4.w += a.w + b4.w;
        }
        const float s = (s4.x + s4.y) + (s4.z + s4.w);

        const int r = Ri - (q >> 1), c = Ci - (q & 1);
        if (r >= 0 && r < NKH && c >= 0 && c < NKW)
            atomicAdd(out + (size_t)(B0 + b) * NK + r * NKW + c, s);
    }
}

extern "C" void kernel_launch(void* const* d_in, const int* in_sizes, int n_in,
                              void* d_out, int out_size)
{
    const float* x      = (const float*)d_in[0];   // (64,1,512,512) fp32
    const float* weight = (const float*)d_in[1];   // (1024,1024)    fp32
    const float* bias   = (const float*)d_in[2];   // (1024,)        fp32
    float*       out    = (float*)d_out;           // (64,32,32)     fp32

    bslc_init<<<(BATCH * NK) / (256 * 4), 256>>>(
        (const float4*)bias, (float4*)out);

    dim3 grid(NC * NC, 2);                         // cell x batch-half
    bslc_main<<<grid, 256>>>(x, weight, out);
}